// round 1
// baseline (speedup 1.0000x reference)
#include <cuda_runtime.h>

#define N_NODES 50000
#define N_EDGES 800000
#define HID 128
#define N_LAYERS 7
#define N_GRAPHS 500
#define N_CLASSES 2

// ---------------- scratch (device globals; no allocs allowed) ----------------
__device__ float g_h0[N_NODES * HID];
__device__ float g_h1[N_NODES * HID];
__device__ float g_agg[N_NODES * HID];
__device__ float g_pooled[N_GRAPHS * HID];
__device__ float g_invdeg[N_NODES];
__device__ int   g_deg[N_NODES];
__device__ int   g_rowptr[N_NODES + 1];
__device__ int   g_cursor[N_NODES];
__device__ int   g_col[N_EDGES];
__device__ int   g_bsum[64];
__device__ int   g_boff[64];

// ---------------- CSR build ----------------
__global__ void k_zero() {
    int i = blockIdx.x * blockDim.x + threadIdx.x;
    if (i < N_NODES) { g_deg[i] = 0; g_cursor[i] = 0; }
    if (i < N_GRAPHS * HID) g_pooled[i] = 0.0f;
}

__global__ void k_hist(const int* __restrict__ dst) {
    int e = blockIdx.x * blockDim.x + threadIdx.x;
    if (e < N_EDGES) atomicAdd(&g_deg[dst[e]], 1);
}

__global__ void k_scanA() {
    __shared__ int s[1024];
    int t = threadIdx.x;
    int idx = blockIdx.x * 1024 + t;
    int v = (idx < N_NODES) ? g_deg[idx] : 0;
    s[t] = v;
    __syncthreads();
    #pragma unroll
    for (int off = 1; off < 1024; off <<= 1) {
        int u = (t >= off) ? s[t - off] : 0;
        __syncthreads();
        s[t] += u;
        __syncthreads();
    }
    if (idx < N_NODES) g_rowptr[idx + 1] = s[t];
    if (t == 1023) g_bsum[blockIdx.x] = s[1023];
}

__global__ void k_scanB(int nb) {
    if (threadIdx.x == 0 && blockIdx.x == 0) {
        int run = 0;
        for (int b = 0; b < nb; b++) { g_boff[b] = run; run += g_bsum[b]; }
        g_rowptr[0] = 0;
    }
}

__global__ void k_scanC() {
    int t = threadIdx.x;
    int idx = blockIdx.x * 1024 + t;
    if (idx < N_NODES) {
        g_rowptr[idx + 1] += g_boff[blockIdx.x];
        int d = g_deg[idx];
        g_invdeg[idx] = 1.0f / (float)(d > 0 ? d : 1);
    }
}

__global__ void k_fill(const int* __restrict__ src, const int* __restrict__ dst) {
    int e = blockIdx.x * blockDim.x + threadIdx.x;
    if (e < N_EDGES) {
        int d = dst[e];
        int p = atomicAdd(&g_cursor[d], 1);
        g_col[g_rowptr[d] + p] = src[e];
    }
}

// ---------------- neighbor mean aggregation: warp per node, gather from L2 ----------------
__global__ void k_agg(const float* __restrict__ h) {
    int w = (blockIdx.x * blockDim.x + threadIdx.x) >> 5;
    int lane = threadIdx.x & 31;
    if (w >= N_NODES) return;
    int beg = g_rowptr[w], end = g_rowptr[w + 1];
    int c = lane * 4;
    float4 a0 = make_float4(0.f, 0.f, 0.f, 0.f);
    float4 a1 = make_float4(0.f, 0.f, 0.f, 0.f);
    int e = beg;
    for (; e + 2 <= end; e += 2) {
        int s0 = g_col[e], s1 = g_col[e + 1];
        float4 v0 = *(const float4*)(h + (size_t)s0 * HID + c);
        float4 v1 = *(const float4*)(h + (size_t)s1 * HID + c);
        a0.x += v0.x; a0.y += v0.y; a0.z += v0.z; a0.w += v0.w;
        a1.x += v1.x; a1.y += v1.y; a1.z += v1.z; a1.w += v1.w;
    }
    if (e < end) {
        int s0 = g_col[e];
        float4 v0 = *(const float4*)(h + (size_t)s0 * HID + c);
        a0.x += v0.x; a0.y += v0.y; a0.z += v0.z; a0.w += v0.w;
    }
    float sc = g_invdeg[w];
    float4 o;
    o.x = (a0.x + a1.x) * sc;
    o.y = (a0.y + a1.y) * sc;
    o.z = (a0.z + a1.z) * sc;
    o.w = (a0.w + a1.w) * sc;
    *(float4*)(g_agg + (size_t)w * HID + c) = o;
}

// ---------------- fused SAGE GEMM: out = agg@Wl + bl + h@Wr (+relu) ----------------
// block: 256 threads -> 64 rows x 128 cols, per-thread 8x4 register tile.
__global__ void k_gemm(const float* __restrict__ hin,
                       const float* __restrict__ Wl,
                       const float* __restrict__ Wr,
                       const float* __restrict__ bias,
                       float* __restrict__ out,
                       int relu) {
    __shared__ float sW[16][128];
    __shared__ float sI[16][64];
    int t = threadIdx.x;
    int row0 = blockIdx.x * 64;
    int cx = t & 31;   // col group: cols [cx*4, cx*4+4)
    int ry = t >> 5;   // row group: rows [ry*8, ry*8+8)

    float acc[8][4];
    #pragma unroll
    for (int i = 0; i < 8; i++)
        #pragma unroll
        for (int j = 0; j < 4; j++) acc[i][j] = 0.0f;

    #pragma unroll
    for (int p = 0; p < 2; p++) {
        const float* in = p ? hin : (const float*)g_agg;
        const float* W  = p ? Wr  : Wl;
        for (int kb = 0; kb < 128; kb += 16) {
            // stage W chunk [16][128]: 2048 floats, 2 float4 per thread
            #pragma unroll
            for (int i = 0; i < 2; i++) {
                int f  = (t + i * 256) * 4;
                int k  = f >> 7;
                int cc = f & 127;
                *(float4*)&sW[k][cc] = *(const float4*)(W + (size_t)(kb + k) * 128 + cc);
            }
            // stage input chunk [16 k][64 rows] (transposed on store)
            {
                int r  = t >> 2;
                int k4 = (t & 3) * 4;
                int rg = row0 + r;
                if (rg >= N_NODES) rg = N_NODES - 1;
                float4 v = *(const float4*)(in + (size_t)rg * 128 + kb + k4);
                sI[k4 + 0][r] = v.x;
                sI[k4 + 1][r] = v.y;
                sI[k4 + 2][r] = v.z;
                sI[k4 + 3][r] = v.w;
            }
            __syncthreads();
            #pragma unroll
            for (int k = 0; k < 16; k++) {
                float4 w4 = *(float4*)&sW[k][cx * 4];
                #pragma unroll
                for (int i = 0; i < 8; i++) {
                    float a = sI[k][ry * 8 + i];   // broadcast within warp
                    acc[i][0] += a * w4.x;
                    acc[i][1] += a * w4.y;
                    acc[i][2] += a * w4.z;
                    acc[i][3] += a * w4.w;
                }
            }
            __syncthreads();
        }
    }

    float4 b4 = *(const float4*)(bias + cx * 4);
    #pragma unroll
    for (int i = 0; i < 8; i++) {
        int r = row0 + ry * 8 + i;
        if (r < N_NODES) {
            float4 o;
            o.x = acc[i][0] + b4.x;
            o.y = acc[i][1] + b4.y;
            o.z = acc[i][2] + b4.z;
            o.w = acc[i][3] + b4.w;
            if (relu) {
                o.x = fmaxf(o.x, 0.f); o.y = fmaxf(o.y, 0.f);
                o.z = fmaxf(o.z, 0.f); o.w = fmaxf(o.w, 0.f);
            }
            *(float4*)(out + (size_t)r * 128 + cx * 4) = o;
        }
    }
}

// ---------------- global_add_pool ----------------
__global__ void k_pool(const float* __restrict__ h, const int* __restrict__ batch) {
    int w = (blockIdx.x * blockDim.x + threadIdx.x) >> 5;
    int lane = threadIdx.x & 31;
    if (w >= N_NODES) return;
    int g = batch[w];
    int c = lane * 4;
    float4 v = *(const float4*)(h + (size_t)w * HID + c);
    atomicAdd(&g_pooled[g * HID + c + 0], v.x);
    atomicAdd(&g_pooled[g * HID + c + 1], v.y);
    atomicAdd(&g_pooled[g * HID + c + 2], v.z);
    atomicAdd(&g_pooled[g * HID + c + 3], v.w);
}

// ---------------- output head: warp per graph ----------------
__global__ void k_final(const float* __restrict__ Wout,
                        const float* __restrict__ bout,
                        float* __restrict__ out) {
    int w = (blockIdx.x * blockDim.x + threadIdx.x) >> 5;
    int lane = threadIdx.x & 31;
    if (w >= N_GRAPHS) return;
    float s0 = 0.f, s1 = 0.f;
    #pragma unroll
    for (int i = 0; i < 4; i++) {
        int k = lane * 4 + i;
        float pv = g_pooled[w * HID + k];
        s0 += pv * Wout[k * 2 + 0];
        s1 += pv * Wout[k * 2 + 1];
    }
    #pragma unroll
    for (int off = 16; off; off >>= 1) {
        s0 += __shfl_xor_sync(0xFFFFFFFFu, s0, off);
        s1 += __shfl_xor_sync(0xFFFFFFFFu, s1, off);
    }
    if (lane == 0) {
        out[w * 2 + 0] = s0 + bout[0];
        out[w * 2 + 1] = s1 + bout[1];
    }
}

// ---------------- launch ----------------
extern "C" void kernel_launch(void* const* d_in, const int* in_sizes, int n_in,
                              void* d_out, int out_size) {
    const float* x     = (const float*)d_in[0];
    const int*   ei    = (const int*)d_in[1];
    const int*   src   = ei;
    const int*   dst   = ei + N_EDGES;
    const int*   batch = (const int*)d_in[2];
    const float* Wl    = (const float*)d_in[3];
    const float* Wr    = (const float*)d_in[4];
    const float* bl    = (const float*)d_in[5];
    const float* Wout  = (const float*)d_in[6];
    const float* bout  = (const float*)d_in[7];
    float* out = (float*)d_out;

    float *h0, *h1;
    cudaGetSymbolAddress((void**)&h0, g_h0);
    cudaGetSymbolAddress((void**)&h1, g_h1);

    const int NB = (N_NODES + 1023) / 1024;  // 49

    k_zero<<<(N_GRAPHS * HID + 255) / 256, 256>>>();
    k_hist<<<(N_EDGES + 255) / 256, 256>>>(dst);
    k_scanA<<<NB, 1024>>>();
    k_scanB<<<1, 32>>>(NB);
    k_scanC<<<NB, 1024>>>();
    k_fill<<<(N_EDGES + 255) / 256, 256>>>(src, dst);

    const float* cur = x;
    for (int i = 0; i < N_LAYERS; i++) {
        k_agg<<<(N_NODES * 32 + 255) / 256, 256>>>(cur);
        float* o = (i & 1) ? h1 : h0;
        k_gemm<<<(N_NODES + 63) / 64, 256>>>(cur,
                                             Wl + (size_t)i * HID * HID,
                                             Wr + (size_t)i * HID * HID,
                                             bl + (size_t)i * HID,
                                             o,
                                             (i < N_LAYERS - 1) ? 1 : 0);
        cur = o;
    }
    k_pool<<<(N_NODES * 32 + 255) / 256, 256>>>(cur, batch);
    k_final<<<(N_GRAPHS * 32 + 255) / 256, 256>>>(Wout, bout, out);
}

// round 2
// speedup vs baseline: 1.0001x; 1.0001x over previous
#include <cuda_runtime.h>

#define N_NODES 50000
#define N_EDGES 800000
#define HID 128
#define N_LAYERS 7
#define N_GRAPHS 500
#define N_CLASSES 2

// ---------------- scratch (device globals; no allocs allowed) ----------------
__device__ float g_h0[N_NODES * HID];
__device__ float g_h1[N_NODES * HID];
__device__ float g_agg[N_NODES * HID];
__device__ float g_pooled[N_GRAPHS * HID];
__device__ float g_invdeg[N_NODES];
__device__ int   g_deg[N_NODES];
__device__ int   g_rowptr[N_NODES + 1];
__device__ int   g_cursor[N_NODES];
__device__ int   g_col[N_EDGES];
__device__ int   g_bsum[64];
__device__ int   g_boff[64];

// ---------------- CSR build ----------------
__global__ void k_zero() {
    int i = blockIdx.x * blockDim.x + threadIdx.x;
    if (i < N_NODES) { g_deg[i] = 0; g_cursor[i] = 0; }
    if (i < N_GRAPHS * HID) g_pooled[i] = 0.0f;
}

__global__ void k_hist(const int* __restrict__ dst) {
    int e = blockIdx.x * blockDim.x + threadIdx.x;
    if (e < N_EDGES) atomicAdd(&g_deg[dst[e]], 1);
}

__global__ void k_scanA() {
    __shared__ int s[1024];
    int t = threadIdx.x;
    int idx = blockIdx.x * 1024 + t;
    int v = (idx < N_NODES) ? g_deg[idx] : 0;
    s[t] = v;
    __syncthreads();
    #pragma unroll
    for (int off = 1; off < 1024; off <<= 1) {
        int u = (t >= off) ? s[t - off] : 0;
        __syncthreads();
        s[t] += u;
        __syncthreads();
    }
    if (idx < N_NODES) g_rowptr[idx + 1] = s[t];
    if (t == 1023) g_bsum[blockIdx.x] = s[1023];
}

__global__ void k_scanB(int nb) {
    if (threadIdx.x == 0 && blockIdx.x == 0) {
        int run = 0;
        for (int b = 0; b < nb; b++) { g_boff[b] = run; run += g_bsum[b]; }
        g_rowptr[0] = 0;
    }
}

__global__ void k_scanC() {
    int t = threadIdx.x;
    int idx = blockIdx.x * 1024 + t;
    if (idx < N_NODES) {
        g_rowptr[idx + 1] += g_boff[blockIdx.x];
        int d = g_deg[idx];
        g_invdeg[idx] = 1.0f / (float)(d > 0 ? d : 1);
    }
}

__global__ void k_fill(const int* __restrict__ src, const int* __restrict__ dst) {
    int e = blockIdx.x * blockDim.x + threadIdx.x;
    if (e < N_EDGES) {
        int d = dst[e];
        int p = atomicAdd(&g_cursor[d], 1);
        g_col[g_rowptr[d] + p] = src[e];
    }
}

// ---------------- neighbor mean aggregation: warp per node, gather from L2 ----------------
__global__ void k_agg(const float* __restrict__ h) {
    int w = (blockIdx.x * blockDim.x + threadIdx.x) >> 5;
    int lane = threadIdx.x & 31;
    if (w >= N_NODES) return;
    int beg = g_rowptr[w], end = g_rowptr[w + 1];
    int c = lane * 4;
    float4 a0 = make_float4(0.f, 0.f, 0.f, 0.f);
    float4 a1 = make_float4(0.f, 0.f, 0.f, 0.f);
    int e = beg;
    for (; e + 2 <= end; e += 2) {
        int s0 = g_col[e], s1 = g_col[e + 1];
        float4 v0 = *(const float4*)(h + (size_t)s0 * HID + c);
        float4 v1 = *(const float4*)(h + (size_t)s1 * HID + c);
        a0.x += v0.x; a0.y += v0.y; a0.z += v0.z; a0.w += v0.w;
        a1.x += v1.x; a1.y += v1.y; a1.z += v1.z; a1.w += v1.w;
    }
    if (e < end) {
        int s0 = g_col[e];
        float4 v0 = *(const float4*)(h + (size_t)s0 * HID + c);
        a0.x += v0.x; a0.y += v0.y; a0.z += v0.z; a0.w += v0.w;
    }
    float sc = g_invdeg[w];
    float4 o;
    o.x = (a0.x + a1.x) * sc;
    o.y = (a0.y + a1.y) * sc;
    o.z = (a0.z + a1.z) * sc;
    o.w = (a0.w + a1.w) * sc;
    *(float4*)(g_agg + (size_t)w * HID + c) = o;
}

// ---------------- fused SAGE GEMM: out = agg@Wl + bl + h@Wr (+relu) ----------------
// block: 256 threads -> 64 rows x 128 cols, per-thread 8x4 register tile.
__global__ void k_gemm(const float* __restrict__ hin,
                       const float* __restrict__ Wl,
                       const float* __restrict__ Wr,
                       const float* __restrict__ bias,
                       float* __restrict__ out,
                       int relu) {
    __shared__ float sW[16][128];
    __shared__ float sI[16][64];
    int t = threadIdx.x;
    int row0 = blockIdx.x * 64;
    int cx = t & 31;   // col group: cols [cx*4, cx*4+4)
    int ry = t >> 5;   // row group: rows [ry*8, ry*8+8)

    float acc[8][4];
    #pragma unroll
    for (int i = 0; i < 8; i++)
        #pragma unroll
        for (int j = 0; j < 4; j++) acc[i][j] = 0.0f;

    #pragma unroll
    for (int p = 0; p < 2; p++) {
        const float* in = p ? hin : (const float*)g_agg;
        const float* W  = p ? Wr  : Wl;
        for (int kb = 0; kb < 128; kb += 16) {
            // stage W chunk [16][128]: 2048 floats, 2 float4 per thread
            #pragma unroll
            for (int i = 0; i < 2; i++) {
                int f  = (t + i * 256) * 4;
                int k  = f >> 7;
                int cc = f & 127;
                *(float4*)&sW[k][cc] = *(const float4*)(W + (size_t)(kb + k) * 128 + cc);
            }
            // stage input chunk [16 k][64 rows] (transposed on store)
            {
                int r  = t >> 2;
                int k4 = (t & 3) * 4;
                int rg = row0 + r;
                if (rg >= N_NODES) rg = N_NODES - 1;
                float4 v = *(const float4*)(in + (size_t)rg * 128 + kb + k4);
                sI[k4 + 0][r] = v.x;
                sI[k4 + 1][r] = v.y;
                sI[k4 + 2][r] = v.z;
                sI[k4 + 3][r] = v.w;
            }
            __syncthreads();
            #pragma unroll
            for (int k = 0; k < 16; k++) {
                float4 w4 = *(float4*)&sW[k][cx * 4];
                #pragma unroll
                for (int i = 0; i < 8; i++) {
                    float a = sI[k][ry * 8 + i];   // broadcast within warp
                    acc[i][0] += a * w4.x;
                    acc[i][1] += a * w4.y;
                    acc[i][2] += a * w4.z;
                    acc[i][3] += a * w4.w;
                }
            }
            __syncthreads();
        }
    }

    float4 b4 = *(const float4*)(bias + cx * 4);
    #pragma unroll
    for (int i = 0; i < 8; i++) {
        int r = row0 + ry * 8 + i;
        if (r < N_NODES) {
            float4 o;
            o.x = acc[i][0] + b4.x;
            o.y = acc[i][1] + b4.y;
            o.z = acc[i][2] + b4.z;
            o.w = acc[i][3] + b4.w;
            if (relu) {
                o.x = fmaxf(o.x, 0.f); o.y = fmaxf(o.y, 0.f);
                o.z = fmaxf(o.z, 0.f); o.w = fmaxf(o.w, 0.f);
            }
            *(float4*)(out + (size_t)r * 128 + cx * 4) = o;
        }
    }
}

// ---------------- global_add_pool ----------------
__global__ void k_pool(const float* __restrict__ h, const int* __restrict__ batch) {
    int w = (blockIdx.x * blockDim.x + threadIdx.x) >> 5;
    int lane = threadIdx.x & 31;
    if (w >= N_NODES) return;
    int g = batch[w];
    int c = lane * 4;
    float4 v = *(const float4*)(h + (size_t)w * HID + c);
    atomicAdd(&g_pooled[g * HID + c + 0], v.x);
    atomicAdd(&g_pooled[g * HID + c + 1], v.y);
    atomicAdd(&g_pooled[g * HID + c + 2], v.z);
    atomicAdd(&g_pooled[g * HID + c + 3], v.w);
}

// ---------------- output head: warp per graph ----------------
__global__ void k_final(const float* __restrict__ Wout,
                        const float* __restrict__ bout,
                        float* __restrict__ out) {
    int w = (blockIdx.x * blockDim.x + threadIdx.x) >> 5;
    int lane = threadIdx.x & 31;
    if (w >= N_GRAPHS) return;
    float s0 = 0.f, s1 = 0.f;
    #pragma unroll
    for (int i = 0; i < 4; i++) {
        int k = lane * 4 + i;
        float pv = g_pooled[w * HID + k];
        s0 += pv * Wout[k * 2 + 0];
        s1 += pv * Wout[k * 2 + 1];
    }
    #pragma unroll
    for (int off = 16; off; off >>= 1) {
        s0 += __shfl_xor_sync(0xFFFFFFFFu, s0, off);
        s1 += __shfl_xor_sync(0xFFFFFFFFu, s1, off);
    }
    if (lane == 0) {
        out[w * 2 + 0] = s0 + bout[0];
        out[w * 2 + 1] = s1 + bout[1];
    }
}

// ---------------- launch ----------------
extern "C" void kernel_launch(void* const* d_in, const int* in_sizes, int n_in,
                              void* d_out, int out_size) {
    const float* x     = (const float*)d_in[0];
    const int*   ei    = (const int*)d_in[1];
    const int*   src   = ei;
    const int*   dst   = ei + N_EDGES;
    const int*   batch = (const int*)d_in[2];
    const float* Wl    = (const float*)d_in[3];
    const float* Wr    = (const float*)d_in[4];
    const float* bl    = (const float*)d_in[5];
    const float* Wout  = (const float*)d_in[6];
    const float* bout  = (const float*)d_in[7];
    float* out = (float*)d_out;

    float *h0, *h1;
    cudaGetSymbolAddress((void**)&h0, g_h0);
    cudaGetSymbolAddress((void**)&h1, g_h1);

    const int NB = (N_NODES + 1023) / 1024;  // 49

    k_zero<<<(N_GRAPHS * HID + 255) / 256, 256>>>();
    k_hist<<<(N_EDGES + 255) / 256, 256>>>(dst);
    k_scanA<<<NB, 1024>>>();
    k_scanB<<<1, 32>>>(NB);
    k_scanC<<<NB, 1024>>>();
    k_fill<<<(N_EDGES + 255) / 256, 256>>>(src, dst);

    const float* cur = x;
    for (int i = 0; i < N_LAYERS; i++) {
        k_agg<<<(N_NODES * 32 + 255) / 256, 256>>>(cur);
        float* o = (i & 1) ? h1 : h0;
        k_gemm<<<(N_NODES + 63) / 64, 256>>>(cur,
                                             Wl + (size_t)i * HID * HID,
                                             Wr + (size_t)i * HID * HID,
                                             bl + (size_t)i * HID,
                                             o,
                                             (i < N_LAYERS - 1) ? 1 : 0);
        cur = o;
    }
    k_pool<<<(N_NODES * 32 + 255) / 256, 256>>>(cur, batch);
    k_final<<<(N_GRAPHS * 32 + 255) / 256, 256>>>(Wout, bout, out);
}

// round 4
// speedup vs baseline: 1.3222x; 1.3221x over previous
#include <cuda_runtime.h>
#include <cuda_bf16.h>
#include <cstdint>

#define N_NODES 50000
#define N_EDGES 800000
#define HID 128
#define N_LAYERS 7
#define N_GRAPHS 500

// ---------------- scratch (device globals; no allocs allowed) ----------------
__device__ __nv_bfloat16 g_as_hi[N_NODES * HID];      // split of aggregated neighbors
__device__ __nv_bfloat16 g_as_lo[N_NODES * HID];
__device__ __nv_bfloat16 g_hs_hi[N_NODES * HID];      // split of node features
__device__ __nv_bfloat16 g_hs_lo[N_NODES * HID];
__device__ __nv_bfloat16 g_wt[N_LAYERS * 2 * 128 * 256]; // [layer][hi/lo][n=128][k=256]
__device__ float g_pooled[N_GRAPHS * HID];
__device__ float g_invdeg[N_NODES];
__device__ int   g_deg[N_NODES];
__device__ int   g_rowptr[N_NODES + 1];
__device__ int   g_cursor[N_NODES];
__device__ int   g_col[N_EDGES];
__device__ int   g_bsum[64];
__device__ int   g_boff[64];

// ---------------- helpers ----------------
__device__ __forceinline__ uint32_t smem_u32(const void* p) {
    uint32_t a;
    asm("{ .reg .u64 t; cvta.to.shared.u64 t, %1; cvt.u32.u64 %0, t; }" : "=r"(a) : "l"(p));
    return a;
}
__device__ __forceinline__ uint32_t pack_hi2(float a, float b) {
    __nv_bfloat162 t = __floats2bfloat162_rn(a, b);
    return *reinterpret_cast<uint32_t*>(&t);
}
__device__ __forceinline__ uint32_t pack_lo2(float a, float b) {
    float ra = a - __bfloat162float(__float2bfloat16_rn(a));
    float rb = b - __bfloat162float(__float2bfloat16_rn(b));
    __nv_bfloat162 t = __floats2bfloat162_rn(ra, rb);
    return *reinterpret_cast<uint32_t*>(&t);
}
__device__ __forceinline__ float2 up2(uint32_t u) {
    __nv_bfloat162 b = *reinterpret_cast<__nv_bfloat162*>(&u);
    return __bfloat1622float2(b);
}

__device__ __forceinline__ void ldsm_x4(uint32_t* r, uint32_t addr) {
    asm volatile("ldmatrix.sync.aligned.m8n8.x4.shared.b16 {%0,%1,%2,%3}, [%4];"
                 : "=r"(r[0]), "=r"(r[1]), "=r"(r[2]), "=r"(r[3]) : "r"(addr));
}
__device__ __forceinline__ void ldsm_x2(uint32_t* r, uint32_t addr) {
    asm volatile("ldmatrix.sync.aligned.m8n8.x2.shared.b16 {%0,%1}, [%2];"
                 : "=r"(r[0]), "=r"(r[1]) : "r"(addr));
}
__device__ __forceinline__ void mma_bf16(float* c, const uint32_t* a, const uint32_t* b) {
    asm volatile("mma.sync.aligned.m16n8k16.row.col.f32.bf16.bf16.f32 "
                 "{%0,%1,%2,%3}, {%4,%5,%6,%7}, {%8,%9}, {%0,%1,%2,%3};"
                 : "+f"(c[0]), "+f"(c[1]), "+f"(c[2]), "+f"(c[3])
                 : "r"(a[0]), "r"(a[1]), "r"(a[2]), "r"(a[3]), "r"(b[0]), "r"(b[1]));
}

// ---------------- CSR build ----------------
__global__ void k_zero() {
    int i = blockIdx.x * blockDim.x + threadIdx.x;
    if (i < N_NODES) { g_deg[i] = 0; g_cursor[i] = 0; }
    if (i < N_GRAPHS * HID) g_pooled[i] = 0.0f;
}
__global__ void k_hist(const int* __restrict__ dst) {
    int e = blockIdx.x * blockDim.x + threadIdx.x;
    if (e < N_EDGES) atomicAdd(&g_deg[dst[e]], 1);
}
__global__ void k_scanA() {
    __shared__ int s[1024];
    int t = threadIdx.x;
    int idx = blockIdx.x * 1024 + t;
    int v = (idx < N_NODES) ? g_deg[idx] : 0;
    s[t] = v;
    __syncthreads();
    #pragma unroll
    for (int off = 1; off < 1024; off <<= 1) {
        int u = (t >= off) ? s[t - off] : 0;
        __syncthreads();
        s[t] += u;
        __syncthreads();
    }
    if (idx < N_NODES) g_rowptr[idx + 1] = s[t];
    if (t == 1023) g_bsum[blockIdx.x] = s[1023];
}
__global__ void k_scanB(int nb) {
    if (threadIdx.x == 0 && blockIdx.x == 0) {
        int run = 0;
        for (int b = 0; b < nb; b++) { g_boff[b] = run; run += g_bsum[b]; }
        g_rowptr[0] = 0;
    }
}
__global__ void k_scanC() {
    int t = threadIdx.x;
    int idx = blockIdx.x * 1024 + t;
    if (idx < N_NODES) {
        g_rowptr[idx + 1] += g_boff[blockIdx.x];
        int d = g_deg[idx];
        g_invdeg[idx] = 1.0f / (float)(d > 0 ? d : 1);
    }
}
__global__ void k_fill(const int* __restrict__ src, const int* __restrict__ dst) {
    int e = blockIdx.x * blockDim.x + threadIdx.x;
    if (e < N_EDGES) {
        int d = dst[e];
        int p = atomicAdd(&g_cursor[d], 1);
        g_col[g_rowptr[d] + p] = src[e];
    }
}

// ---------------- weight prep: transpose + split to bf16 hi/lo ----------------
// g_wt layout per layer: [hi: n(128) x k(256)] then [lo: n x k], k-contiguous.
__global__ void k_prep_w(const float* __restrict__ Wl, const float* __restrict__ Wr) {
    int idx = blockIdx.x * blockDim.x + threadIdx.x;
    if (idx >= N_LAYERS * 128 * 256) return;
    int l = idx >> 15;
    int r = idx & 32767;
    int n = r >> 8;
    int k = r & 255;
    float w = (k < 128) ? Wl[((size_t)l * 128 + k) * 128 + n]
                        : Wr[((size_t)l * 128 + (k - 128)) * 128 + n];
    __nv_bfloat16 hb = __float2bfloat16_rn(w);
    float lf = w - __bfloat162float(hb);
    size_t bo = (size_t)l * 65536;
    g_wt[bo + (size_t)n * 256 + k] = hb;
    g_wt[bo + 32768 + (size_t)n * 256 + k] = __float2bfloat16_rn(lf);
}

// ---------------- split x (layer-0 node features) into bf16 hi/lo ----------------
__global__ void k_split_x(const float* __restrict__ x) {
    int i = blockIdx.x * blockDim.x + threadIdx.x;
    if (i >= N_NODES * HID / 4) return;
    float4 v = *(const float4*)(x + (size_t)i * 4);
    uint2 h, l;
    h.x = pack_hi2(v.x, v.y); h.y = pack_hi2(v.z, v.w);
    l.x = pack_lo2(v.x, v.y); l.y = pack_lo2(v.z, v.w);
    *(uint2*)(g_hs_hi + (size_t)i * 4) = h;
    *(uint2*)(g_hs_lo + (size_t)i * 4) = l;
}

// ---------------- neighbor mean aggregation (gather hi+lo) -> split bf16 out ----------------
__global__ void k_agg() {
    int w = (blockIdx.x * blockDim.x + threadIdx.x) >> 5;
    int lane = threadIdx.x & 31;
    if (w >= N_NODES) return;
    int beg = g_rowptr[w], end = g_rowptr[w + 1];
    int c = lane * 4;
    float a0 = 0.f, a1 = 0.f, a2 = 0.f, a3 = 0.f;
    for (int e = beg; e < end; e++) {
        int s0 = g_col[e];
        uint2 hh = *(const uint2*)(g_hs_hi + (size_t)s0 * HID + c);
        uint2 ll = *(const uint2*)(g_hs_lo + (size_t)s0 * HID + c);
        float2 h0 = up2(hh.x), h1 = up2(hh.y);
        float2 l0 = up2(ll.x), l1 = up2(ll.y);
        a0 += h0.x + l0.x;
        a1 += h0.y + l0.y;
        a2 += h1.x + l1.x;
        a3 += h1.y + l1.y;
    }
    float sc = g_invdeg[w];
    a0 *= sc; a1 *= sc; a2 *= sc; a3 *= sc;
    uint2 hh, ll;
    hh.x = pack_hi2(a0, a1); hh.y = pack_hi2(a2, a3);
    ll.x = pack_lo2(a0, a1); ll.y = pack_lo2(a2, a3);
    *(uint2*)(g_as_hi + (size_t)w * HID + c) = hh;
    *(uint2*)(g_as_lo + (size_t)w * HID + c) = ll;
}

// ---------------- HMMA fused SAGE GEMM ----------------
// out[128,128] = [agg | h] (K=256, split-bf16) @ Wt (split-bf16) + b, fp32 accum.
// D = Ahi*Bhi + Ahi*Blo + Alo*Bhi.  8 warps: warp tile 64x32 (warpM=wid>>2, warpN=wid&3).
// SMEM tiles: [128 rows][k=32] bf16, row stride 40 elems (80 B) -> conflict-free ldmatrix.
#define RS 40   // row stride in bf16 elems

__global__ void __launch_bounds__(256, 1) k_gemm(
    const __nv_bfloat16* __restrict__ wt,   // layer base: [hi 128x256 | lo 128x256]
    const float* __restrict__ bias,
    int doRelu)
{
    __shared__ __align__(16) __nv_bfloat16 sAh[128 * RS];
    __shared__ __align__(16) __nv_bfloat16 sAl[128 * RS];
    __shared__ __align__(16) __nv_bfloat16 sBh[128 * RS];
    __shared__ __align__(16) __nv_bfloat16 sBl[128 * RS];
    __shared__ float sBias[128];

    int t = threadIdx.x;
    int lane = t & 31;
    int wid = t >> 5;
    int warpM = wid >> 2;      // 0..1
    int warpN = wid & 3;       // 0..3
    int row0 = blockIdx.x * 128;

    if (t < 128) sBias[t] = bias[t];

    float c[4][4][4];
    #pragma unroll
    for (int i = 0; i < 4; i++)
        #pragma unroll
        for (int j = 0; j < 4; j++)
            #pragma unroll
            for (int q = 0; q < 4; q++) c[i][j][q] = 0.0f;

    uint32_t bAh = smem_u32(sAh), bAl = smem_u32(sAl);
    uint32_t bBh = smem_u32(sBh), bBl = smem_u32(sBl);

    const __nv_bfloat16* wHi = wt;
    const __nv_bfloat16* wLo = wt + 32768;

    for (int c8 = 0; c8 < 8; c8++) {
        __syncthreads();
        // ---- stage: 512 x 16B per matrix, 2 per thread per matrix ----
        const __nv_bfloat16* srcHi = (c8 < 4) ? g_as_hi : g_hs_hi;
        const __nv_bfloat16* srcLo = (c8 < 4) ? g_as_lo : g_hs_lo;
        int kcol = (c8 & 3) * 32;
        #pragma unroll
        for (int i = 0; i < 2; i++) {
            int idx = t + i * 256;            // 0..511
            int row = idx >> 2, c16 = idx & 3;
            int sm = row * RS + c16 * 8;
            int rg = row0 + row;
            if (rg > N_NODES - 1) rg = N_NODES - 1;
            size_t ao = (size_t)rg * 128 + kcol + c16 * 8;
            *(uint4*)(sAh + sm) = *(const uint4*)(srcHi + ao);
            *(uint4*)(sAl + sm) = *(const uint4*)(srcLo + ao);
            size_t wo = (size_t)row * 256 + c8 * 32 + c16 * 8;   // row = n index
            *(uint4*)(sBh + sm) = *(const uint4*)(wHi + wo);
            *(uint4*)(sBl + sm) = *(const uint4*)(wLo + wo);
        }
        __syncthreads();

        // ---- compute: 2 k16 steps ----
        #pragma unroll
        for (int kk = 0; kk < 2; kk++) {
            uint32_t ah[4][4], al[4][4], bh[4][2], bl[4][2];
            int ar = warpM * 64 + (lane & 15);
            int akc = kk * 16 + (lane >> 4) * 8;
            #pragma unroll
            for (int mt = 0; mt < 4; mt++) {
                uint32_t off = (uint32_t)((ar + mt * 16) * RS + akc) * 2;
                ldsm_x4(ah[mt], bAh + off);
                ldsm_x4(al[mt], bAl + off);
            }
            int br = warpN * 32 + (lane & 7);
            int bkc = kk * 16 + ((lane >> 3) & 1) * 8;
            #pragma unroll
            for (int nt = 0; nt < 4; nt++) {
                uint32_t off = (uint32_t)((br + nt * 8) * RS + bkc) * 2;
                ldsm_x2(bh[nt], bBh + off);
                ldsm_x2(bl[nt], bBl + off);
            }
            #pragma unroll
            for (int mt = 0; mt < 4; mt++)
                #pragma unroll
                for (int nt = 0; nt < 4; nt++) {
                    mma_bf16(c[mt][nt], ah[mt], bh[nt]);
                    mma_bf16(c[mt][nt], ah[mt], bl[nt]);
                    mma_bf16(c[mt][nt], al[mt], bh[nt]);
                }
        }
    }

    // ---- epilogue: bias + relu + split-store hi/lo bf16 ----
    int g = lane >> 2;
    int cc = (lane & 3) * 2;
    #pragma unroll
    for (int mt = 0; mt < 4; mt++) {
        #pragma unroll
        for (int nt = 0; nt < 4; nt++) {
            int col = warpN * 32 + nt * 8 + cc;
            float b0 = sBias[col], b1 = sBias[col + 1];
            #pragma unroll
            for (int half = 0; half < 2; half++) {
                int r = row0 + warpM * 64 + mt * 16 + g + half * 8;
                if (r < N_NODES) {
                    float v0 = c[mt][nt][half * 2 + 0] + b0;
                    float v1 = c[mt][nt][half * 2 + 1] + b1;
                    if (doRelu) { v0 = fmaxf(v0, 0.f); v1 = fmaxf(v1, 0.f); }
                    *(uint32_t*)(g_hs_hi + (size_t)r * 128 + col) = pack_hi2(v0, v1);
                    *(uint32_t*)(g_hs_lo + (size_t)r * 128 + col) = pack_lo2(v0, v1);
                }
            }
        }
    }
}

// ---------------- global_add_pool (reads hi+lo) ----------------
__global__ void k_pool(const int* __restrict__ batch) {
    int w = (blockIdx.x * blockDim.x + threadIdx.x) >> 5;
    int lane = threadIdx.x & 31;
    if (w >= N_NODES) return;
    int g = batch[w];
    int c = lane * 4;
    uint2 hh = *(const uint2*)(g_hs_hi + (size_t)w * HID + c);
    uint2 ll = *(const uint2*)(g_hs_lo + (size_t)w * HID + c);
    float2 h0 = up2(hh.x), h1 = up2(hh.y);
    float2 l0 = up2(ll.x), l1 = up2(ll.y);
    atomicAdd(&g_pooled[g * HID + c + 0], h0.x + l0.x);
    atomicAdd(&g_pooled[g * HID + c + 1], h0.y + l0.y);
    atomicAdd(&g_pooled[g * HID + c + 2], h1.x + l1.x);
    atomicAdd(&g_pooled[g * HID + c + 3], h1.y + l1.y);
}

// ---------------- output head ----------------
__global__ void k_final(const float* __restrict__ Wout,
                        const float* __restrict__ bout,
                        float* __restrict__ out) {
    int w = (blockIdx.x * blockDim.x + threadIdx.x) >> 5;
    int lane = threadIdx.x & 31;
    if (w >= N_GRAPHS) return;
    float s0 = 0.f, s1 = 0.f;
    #pragma unroll
    for (int i = 0; i < 4; i++) {
        int k = lane * 4 + i;
        float pv = g_pooled[w * HID + k];
        s0 += pv * Wout[k * 2 + 0];
        s1 += pv * Wout[k * 2 + 1];
    }
    #pragma unroll
    for (int off = 16; off; off >>= 1) {
        s0 += __shfl_xor_sync(0xFFFFFFFFu, s0, off);
        s1 += __shfl_xor_sync(0xFFFFFFFFu, s1, off);
    }
    if (lane == 0) {
        out[w * 2 + 0] = s0 + bout[0];
        out[w * 2 + 1] = s1 + bout[1];
    }
}

// ---------------- launch ----------------
extern "C" void kernel_launch(void* const* d_in, const int* in_sizes, int n_in,
                              void* d_out, int out_size) {
    const float* x     = (const float*)d_in[0];
    const int*   ei    = (const int*)d_in[1];
    const int*   src   = ei;
    const int*   dst   = ei + N_EDGES;
    const int*   batch = (const int*)d_in[2];
    const float* Wl    = (const float*)d_in[3];
    const float* Wr    = (const float*)d_in[4];
    const float* bl    = (const float*)d_in[5];
    const float* Wout  = (const float*)d_in[6];
    const float* bout  = (const float*)d_in[7];
    float* out = (float*)d_out;

    __nv_bfloat16* wt;
    cudaGetSymbolAddress((void**)&wt, g_wt);

    const int NB = (N_NODES + 1023) / 1024;  // 49

    k_zero<<<(N_GRAPHS * HID + 255) / 256, 256>>>();
    k_hist<<<(N_EDGES + 255) / 256, 256>>>(dst);
    k_scanA<<<NB, 1024>>>();
    k_scanB<<<1, 32>>>(NB);
    k_scanC<<<NB, 1024>>>();
    k_fill<<<(N_EDGES + 255) / 256, 256>>>(src, dst);
    k_prep_w<<<(N_LAYERS * 128 * 256 + 255) / 256, 256>>>(Wl, Wr);
    k_split_x<<<(N_NODES * HID / 4 + 255) / 256, 256>>>(x);

    const int GG = (N_NODES + 127) / 128;  // 391
    for (int i = 0; i < N_LAYERS; i++) {
        k_agg<<<(N_NODES * 32 + 255) / 256, 256>>>();
        k_gemm<<<GG, 256>>>(wt + (size_t)i * 65536,
                            bl + (size_t)i * HID,
                            (i < N_LAYERS - 1) ? 1 : 0);
    }
    k_pool<<<(N_NODES * 32 + 255) / 256, 256>>>(batch);
    k_final<<<(N_GRAPHS * 32 + 255) / 256, 256>>>(Wout, bout, out);
}